// round 13
// baseline (speedup 1.0000x reference)
#include <cuda_runtime.h>
#include <cuda_fp16.h>

// Problem constants (fixed by the dataset)
#define B_COLS    64           // dense columns
#define N_MAX     50048        // neuron count (50000) rounded up
#define NNZ_MAX   800000
// Padded edge capacity: roundup8(NNZ) + 8*N
#define PAD_MAX   (NNZ_MAX + 8 * N_MAX + 64)

// Scratch (no allocation allowed)
__device__ __half2 g_hA[N_MAX * 32];   // fp16 ping-pong dense buffers
__device__ __half2 g_hB[N_MAX * 32];
__device__ int     g_row_ptr[N_MAX + 1];
__device__ float   g_wp[PAD_MAX];      // padded w_vals   (fp32)
__device__ float   g_ap[PAD_MAX];      // padded adj_vals (fp32)
__device__ int     g_cp[PAD_MAX];      // padded cols, premultiplied by 32 (half2 row stride)

// ---------------------------------------------------------------------------
// Build CSR row_ptr from the sorted `rows` array.
// ---------------------------------------------------------------------------
__global__ void build_row_ptr_kernel(const int* __restrict__ rows, int nnz, int n,
                                     int* __restrict__ row_ptr) {
    int i = blockIdx.x * blockDim.x + threadIdx.x;
    if (i >= nnz) return;
    int r = rows[i];
    int rprev = (i == 0) ? -1 : rows[i - 1];
    for (int rr = rprev + 1; rr <= r; rr++) row_ptr[rr] = i;
    if (i == nnz - 1) {
        for (int rr = r + 1; rr <= n; rr++) row_ptr[rr] = nnz;
    }
}

// ---------------------------------------------------------------------------
// fp32 [N,64] -> half2 buffer (pairwise).
// ---------------------------------------------------------------------------
__global__ void f2h_kernel(const float* __restrict__ in, __half2* __restrict__ out,
                           int n2) {
    int i = blockIdx.x * blockDim.x + threadIdx.x;
    if (i < n2) {
        float2 f = reinterpret_cast<const float2*>(in)[i];
        out[i] = __floats2half2_rn(f.x, f.y);
    }
}

// ---------------------------------------------------------------------------
// Scatter edges into the padded 8-aligned layout.
// pstart(r) = roundup8(row_ptr[r]) + 8*r  (8-aligned; capacity >= roundup8(len);
// proof: roundup8(a+len)+8 >= roundup8(a)+roundup8(len) for all a,len).
// The LAST edge of each row zero-fills its row's <=7 padding slots, so no
// separate zero-fill pass over the 1.25M-slot arrays is needed.
// Padding slots: val=0, col=0 -> contribute exactly 0 to the sum.
// ---------------------------------------------------------------------------
__global__ void pack_kernel(const float* __restrict__ w_vals,
                            const float* __restrict__ adj_vals,
                            const int* __restrict__ rows,
                            const int* __restrict__ cols,
                            const int* __restrict__ row_ptr,
                            float* __restrict__ wp, float* __restrict__ ap,
                            int* __restrict__ cp, int nnz) {
    int i = blockIdx.x * blockDim.x + threadIdx.x;
    if (i >= nnz) return;
    int r = rows[i];
    int s = row_ptr[r];
    int base = ((s + 7) & ~7) + 8 * r;
    int dst = base + (i - s);
    wp[dst] = w_vals[i];
    ap[dst] = adj_vals[i];
    cp[dst] = cols[i] * 32;          // half2 index premultiplied
    bool last = (i == nnz - 1) || (rows[i + 1] != r);
    if (last) {
        int len  = i + 1 - s;
        int pend = base + ((len + 7) & ~7);
        for (int d = dst + 1; d < pend; d++) { wp[d] = 0.0f; ap[d] = 0.0f; cp[d] = 0; }
    }
}

// ---------------------------------------------------------------------------
// Padded fp16-gather CSR SpMM:
//   out[r,:] = sum_e vals[e] * x[cols[e],:]  (+ bias[r])
// One warp per row (grid-stride). Lane l owns dense cols {2l,2l+1} as one
// __half2: the per-edge gather is a single 128B, SINGLE-wavefront LDG.32
// (cross-LDG 1.0 cyc/wf rate instead of the 2x128B LDG.64 replay at 2.07).
// Padded layout -> body is ONLY the 8-edge vectorized loop (no peel/tail).
// fp32 vals, fp32 accumulation; intermediates stored fp16; final layer fp32.
// Streaming hints on metadata keep L1 for the x gathers.
// ---------------------------------------------------------------------------
template <bool HAS_BIAS, bool OUT_FP32>
__global__ void __launch_bounds__(256, 8)
spmm_hp_kernel(const float* __restrict__ vals, const int* __restrict__ colsx32,
               const int* __restrict__ row_ptr, const __half2* __restrict__ xin,
               const float* __restrict__ bias, void* __restrict__ out, int n) {
    const int lane   = threadIdx.x & 31;
    const int warpId = (blockIdx.x * blockDim.x + threadIdx.x) >> 5;
    const int nWarps = (gridDim.x * blockDim.x) >> 5;

    const __half2* __restrict__ xl = xin + lane;   // lane-offset base

    for (int row = warpId; row < n; row += nWarps) {
        int s0 = row_ptr[row];
        int e0 = row_ptr[row + 1];
        int k  = ((s0 + 7) & ~7) + 8 * row;          // padded, 8-aligned start
        int e  = k + ((e0 - s0 + 7) & ~7);           // padded end (multiple of 8)

        float accx = 0.0f, accy = 0.0f;

        for (; k < e; k += 8) {
            float4 v0 = __ldcs(reinterpret_cast<const float4*>(vals + k));
            float4 v1 = __ldcs(reinterpret_cast<const float4*>(vals + k + 4));
            int4   c0 = __ldcs(reinterpret_cast<const int4*>(colsx32 + k));
            int4   c1 = __ldcs(reinterpret_cast<const int4*>(colsx32 + k + 4));
            __half2 h0 = xl[c0.x];
            __half2 h1 = xl[c0.y];
            __half2 h2 = xl[c0.z];
            __half2 h3 = xl[c0.w];
            __half2 h4 = xl[c1.x];
            __half2 h5 = xl[c1.y];
            __half2 h6 = xl[c1.z];
            __half2 h7 = xl[c1.w];
            float2 a0 = __half22float2(h0);
            float2 a1 = __half22float2(h1);
            float2 a2 = __half22float2(h2);
            float2 a3 = __half22float2(h3);
            float2 a4 = __half22float2(h4);
            float2 a5 = __half22float2(h5);
            float2 a6 = __half22float2(h6);
            float2 a7 = __half22float2(h7);
            accx = fmaf(v0.x, a0.x, accx); accy = fmaf(v0.x, a0.y, accy);
            accx = fmaf(v0.y, a1.x, accx); accy = fmaf(v0.y, a1.y, accy);
            accx = fmaf(v0.z, a2.x, accx); accy = fmaf(v0.z, a2.y, accy);
            accx = fmaf(v0.w, a3.x, accx); accy = fmaf(v0.w, a3.y, accy);
            accx = fmaf(v1.x, a4.x, accx); accy = fmaf(v1.x, a4.y, accy);
            accx = fmaf(v1.y, a5.x, accx); accy = fmaf(v1.y, a5.y, accy);
            accx = fmaf(v1.z, a6.x, accx); accy = fmaf(v1.z, a6.y, accy);
            accx = fmaf(v1.w, a7.x, accx); accy = fmaf(v1.w, a7.y, accy);
        }

        if (HAS_BIAS) {
            float b = bias[row];
            accx += b; accy += b;
        }
        if (OUT_FP32) {
            float2 r; r.x = accx; r.y = accy;
            reinterpret_cast<float2*>(out)[row * 32 + lane] = r;
        } else {
            reinterpret_cast<__half2*>(out)[row * 32 + lane] =
                __floats2half2_rn(accx, accy);
        }
    }
}

extern "C" void kernel_launch(void* const* d_in, const int* in_sizes, int n_in,
                              void* d_out, int out_size) {
    const float* x        = (const float*)d_in[0];   // [N, 64]
    const float* adj_vals = (const float*)d_in[1];   // [NNZ]
    const float* w_vals   = (const float*)d_in[2];   // [NNZ]
    const float* bias     = (const float*)d_in[3];   // [N]
    const int*   rows     = (const int*)d_in[4];     // [NNZ] sorted
    const int*   cols     = (const int*)d_in[5];     // [NNZ]
    // n_layers (d_in[6]) lives on device; the problem fixes it at 3.

    const int N   = in_sizes[0] / B_COLS;
    const int NNZ = in_sizes[1];

    __half2* hA = nullptr; __half2* hB = nullptr; int* row_ptr = nullptr;
    float* wp = nullptr; float* ap = nullptr; int* cp = nullptr;
    cudaGetSymbolAddress((void**)&hA, g_hA);
    cudaGetSymbolAddress((void**)&hB, g_hB);
    cudaGetSymbolAddress((void**)&row_ptr, g_row_ptr);
    cudaGetSymbolAddress((void**)&wp, g_wp);
    cudaGetSymbolAddress((void**)&ap, g_ap);
    cudaGetSymbolAddress((void**)&cp, g_cp);

    float* outp = (float*)d_out;

    // 1) row_ptr
    {
        int threads = 256;
        int blocks = (NNZ + threads - 1) / threads;
        build_row_ptr_kernel<<<blocks, threads>>>(rows, NNZ, N, row_ptr);
    }
    // 2) x -> fp16  (independent of row_ptr; runs concurrently-ish in stream order)
    {
        int n2 = N * 32;
        int threads = 256;
        int blocks = (n2 + threads - 1) / threads;
        f2h_kernel<<<blocks, threads>>>(x, hA, n2);
    }
    // 3) padded edge format (shared by all six SpMMs); pads are filled inline.
    {
        int threads = 256;
        int blocks = (NNZ + threads - 1) / threads;
        pack_kernel<<<blocks, threads>>>(w_vals, adj_vals, rows, cols, row_ptr,
                                         wp, ap, cp, NNZ);
    }

    // 4) three layers, two SpMMs each; final SpMM writes fp32 to d_out.
    const int threads = 256;
    const int blocks  = 1184;   // one resident wave, grid-stride over rows

    // layer 1
    spmm_hp_kernel<false, false><<<blocks, threads>>>(wp, cp, row_ptr, hA, nullptr, hB, N);
    spmm_hp_kernel<true,  false><<<blocks, threads>>>(ap, cp, row_ptr, hB, bias,    hA, N);
    // layer 2
    spmm_hp_kernel<false, false><<<blocks, threads>>>(wp, cp, row_ptr, hA, nullptr, hB, N);
    spmm_hp_kernel<true,  false><<<blocks, threads>>>(ap, cp, row_ptr, hB, bias,    hA, N);
    // layer 3
    spmm_hp_kernel<false, false><<<blocks, threads>>>(wp, cp, row_ptr, hA, nullptr, hB, N);
    spmm_hp_kernel<true,  true ><<<blocks, threads>>>(ap, cp, row_ptr, hB, bias,    outp, N);
}